// round 7
// baseline (speedup 1.0000x reference)
#include <cuda_runtime.h>
#include <cuda_fp16.h>

#define GROWS 1028
#define GCOLS 1028
#define NCELL (GROWS * GCOLS)

// Pair layout: g_pair[r*GCOLS+c] = 8 fp16 values
//   { coeffs[r, c..c+3], coeffs[r+1, c..c+3] }
// 16 bytes, 16B-aligned -> one LDG.128 fetches two stencil rows.
// Table: 1028*1028*16B = 16.9 MB (L2-resident).
struct __align__(16) Pair8 { __half2 h[4]; };
__device__ Pair8 g_pair[NCELL];

__global__ void expand_kernel(const float* __restrict__ coeffs) {
    int idx = blockIdx.x * blockDim.x + threadIdx.x;
    if (idx >= NCELL) return;
    int r = idx / GCOLS;
    int c = idx - r * GCOLS;
    int c1 = min(c + 1, GCOLS - 1);
    int c2 = min(c + 2, GCOLS - 1);
    int c3 = min(c + 3, GCOLS - 1);
    const float* row0 = coeffs + r * GCOLS;
    const float* row1 = coeffs + min(r + 1, GROWS - 1) * GCOLS;

    Pair8 v;
    v.h[0] = __floats2half2_rn(__ldg(row0 + c),  __ldg(row0 + c1));
    v.h[1] = __floats2half2_rn(__ldg(row0 + c2), __ldg(row0 + c3));
    v.h[2] = __floats2half2_rn(__ldg(row1 + c),  __ldg(row1 + c1));
    v.h[3] = __floats2half2_rn(__ldg(row1 + c2), __ldg(row1 + c3));
    g_pair[idx] = v;  // single 16B store
}

// Evaluate one point given its two stencil uint4s (already loaded).
__device__ __forceinline__ float eval_point(
    float xn0, float xn1, uint4 au, uint4 bu)
{
    float P0 = floorf(xn0), P1 = floorf(xn1);
    float t0 = xn0 - P0,    t1 = xn1 - P1;

    float o1 = 1.0f - t1;
    float t1sq = t1 * t1, o1sq = o1 * o1;
    float w1a = o1sq * o1;
    float w1b = fmaf(fmaf(3.0f, t1, -6.0f), t1sq, 4.0f);
    float w1c = fmaf(fmaf(3.0f, o1, -6.0f), o1sq, 4.0f);
    float w1d = t1sq * t1;

    float o0 = 1.0f - t0;
    float t0sq = t0 * t0, o0sq = o0 * o0;
    float w0a = o0sq * o0;
    float w0b = fmaf(fmaf(3.0f, t0, -6.0f), t0sq, 4.0f);
    float w0c = fmaf(fmaf(3.0f, o0, -6.0f), o0sq, 4.0f);
    float w0d = t0sq * t0;

    __half2* ah = reinterpret_cast<__half2*>(&au);
    __half2* bh = reinterpret_cast<__half2*>(&bu);
    float2 r0lo = __half22float2(ah[0]), r0hi = __half22float2(ah[1]);
    float2 r1lo = __half22float2(ah[2]), r1hi = __half22float2(ah[3]);
    float2 r2lo = __half22float2(bh[0]), r2hi = __half22float2(bh[1]);
    float2 r3lo = __half22float2(bh[2]), r3hi = __half22float2(bh[3]);

    float s0 = fmaf(r0lo.x, w1a, fmaf(r0lo.y, w1b, fmaf(r0hi.x, w1c, r0hi.y * w1d)));
    float s1 = fmaf(r1lo.x, w1a, fmaf(r1lo.y, w1b, fmaf(r1hi.x, w1c, r1hi.y * w1d)));
    float s2 = fmaf(r2lo.x, w1a, fmaf(r2lo.y, w1b, fmaf(r2hi.x, w1c, r2hi.y * w1d)));
    float s3 = fmaf(r3lo.x, w1a, fmaf(r3lo.y, w1b, fmaf(r3hi.x, w1c, r3hi.y * w1d)));

    return fmaf(s0, w0a, fmaf(s1, w0b, fmaf(s2, w0c, s3 * w0d)));
}

__device__ __forceinline__ int stencil_base(float xn0, float xn1) {
    int r0 = (int)floorf(xn0) + 1;
    int c0 = (int)floorf(xn1) + 1;
    r0 = min(max(r0, 0), GROWS - 4);
    c0 = min(max(c0, 0), GCOLS - 4);
    return r0 * GCOLS + c0;
}

// 2 points per thread: 4 independent stencil gathers in flight (MLP=4+).
__global__ void __launch_bounds__(256) spline_kernel(
    const float4* __restrict__ x2, float2* __restrict__ out, int npair)
{
    int i = blockIdx.x * blockDim.x + threadIdx.x;
    if (i >= npair) return;

    float4 p = __ldg(&x2[i]);  // coords of points 2i (x,y) and 2i+1 (z,w)

    float a0 = fmaf(p.x, 1024.0f, -0.5f);
    float a1 = fmaf(p.y, 1024.0f, -0.5f);
    float b0 = fmaf(p.z, 1024.0f, -0.5f);
    float b1 = fmaf(p.w, 1024.0f, -0.5f);

    bool va = (a0 > -2.0f) && (a0 < 1024.0f) && (a1 > -2.0f) && (a1 < 1024.0f);
    bool vb = (b0 > -2.0f) && (b0 < 1024.0f) && (b1 > -2.0f) && (b1 < 1024.0f);

    int baseA = stencil_base(a0, a1);
    int baseB = stencil_base(b0, b1);

    // Issue all 4 gathers before any math.
    const uint4* tab = reinterpret_cast<const uint4*>(g_pair);
    uint4 Aa = __ldg(tab + baseA);
    uint4 Ab = __ldg(tab + baseA + 2 * GCOLS);
    uint4 Ba = __ldg(tab + baseB);
    uint4 Bb = __ldg(tab + baseB + 2 * GCOLS);

    float ra = eval_point(a0, a1, Aa, Ab);
    float rb = eval_point(b0, b1, Ba, Bb);

    float2 o;
    o.x = va ? ra : 0.0f;
    o.y = vb ? rb : 0.0f;
    out[i] = o;
}

extern "C" void kernel_launch(void* const* d_in, const int* in_sizes, int n_in,
                              void* d_out, int out_size) {
    const float4* x2 = (const float4*)d_in[0];    // [N/2] float4 (2 points)
    const float* coeffs = (const float*)d_in[1];  // [1028,1028] float32
    float2* out = (float2*)d_out;                 // [N/2] float2
    int n = out_size;                             // 2097152 (even)
    int npair = n >> 1;

    expand_kernel<<<(NCELL + 255) / 256, 256>>>(coeffs);
    spline_kernel<<<(npair + 255) / 256, 256>>>(x2, out, npair);
}

// round 8
// speedup vs baseline: 1.2515x; 1.2515x over previous
#include <cuda_runtime.h>
#include <cuda_fp16.h>

#define GROWS 1028
#define GCOLS 1028
#define NCELL (GROWS * GCOLS)

// Pair layout: g_pair[r*GCOLS+c] = 8 fp16 values
//   { coeffs[r, c..c+3], coeffs[r+1, c..c+3] }
// 16 bytes, 16B-aligned -> one LDG.128 fetches two stencil rows.
// Table: 1028*1028*16B = 16.9 MB.
struct __align__(16) Pair8 { __half2 h[4]; };
__device__ Pair8 g_pair[NCELL];

__global__ void expand_kernel(const float* __restrict__ coeffs) {
    int idx = blockIdx.x * blockDim.x + threadIdx.x;
    if (idx >= NCELL) return;
    int r = idx / GCOLS;
    int c = idx - r * GCOLS;
    int c1 = min(c + 1, GCOLS - 1);
    int c2 = min(c + 2, GCOLS - 1);
    int c3 = min(c + 3, GCOLS - 1);
    const float* row0 = coeffs + r * GCOLS;
    const float* row1 = coeffs + min(r + 1, GROWS - 1) * GCOLS;

    Pair8 v;
    v.h[0] = __floats2half2_rn(__ldg(row0 + c),  __ldg(row0 + c1));
    v.h[1] = __floats2half2_rn(__ldg(row0 + c2), __ldg(row0 + c3));
    v.h[2] = __floats2half2_rn(__ldg(row1 + c),  __ldg(row1 + c1));
    v.h[3] = __floats2half2_rn(__ldg(row1 + c2), __ldg(row1 + c3));
    g_pair[idx] = v;  // single 16B store
}

// Evaluate one point given its two stencil uint4s (already loaded).
__device__ __forceinline__ float eval_point(
    float xn0, float xn1, uint4 au, uint4 bu)
{
    float P0 = floorf(xn0), P1 = floorf(xn1);
    float t0 = xn0 - P0,    t1 = xn1 - P1;

    float o1 = 1.0f - t1;
    float t1sq = t1 * t1, o1sq = o1 * o1;
    float w1a = o1sq * o1;
    float w1b = fmaf(fmaf(3.0f, t1, -6.0f), t1sq, 4.0f);
    float w1c = fmaf(fmaf(3.0f, o1, -6.0f), o1sq, 4.0f);
    float w1d = t1sq * t1;

    float o0 = 1.0f - t0;
    float t0sq = t0 * t0, o0sq = o0 * o0;
    float w0a = o0sq * o0;
    float w0b = fmaf(fmaf(3.0f, t0, -6.0f), t0sq, 4.0f);
    float w0c = fmaf(fmaf(3.0f, o0, -6.0f), o0sq, 4.0f);
    float w0d = t0sq * t0;

    __half2* ah = reinterpret_cast<__half2*>(&au);
    __half2* bh = reinterpret_cast<__half2*>(&bu);
    float2 r0lo = __half22float2(ah[0]), r0hi = __half22float2(ah[1]);
    float2 r1lo = __half22float2(ah[2]), r1hi = __half22float2(ah[3]);
    float2 r2lo = __half22float2(bh[0]), r2hi = __half22float2(bh[1]);
    float2 r3lo = __half22float2(bh[2]), r3hi = __half22float2(bh[3]);

    float s0 = fmaf(r0lo.x, w1a, fmaf(r0lo.y, w1b, fmaf(r0hi.x, w1c, r0hi.y * w1d)));
    float s1 = fmaf(r1lo.x, w1a, fmaf(r1lo.y, w1b, fmaf(r1hi.x, w1c, r1hi.y * w1d)));
    float s2 = fmaf(r2lo.x, w1a, fmaf(r2lo.y, w1b, fmaf(r2hi.x, w1c, r2hi.y * w1d)));
    float s3 = fmaf(r3lo.x, w1a, fmaf(r3lo.y, w1b, fmaf(r3hi.x, w1c, r3hi.y * w1d)));

    return fmaf(s0, w0a, fmaf(s1, w0b, fmaf(s2, w0c, s3 * w0d)));
}

__device__ __forceinline__ int stencil_base(float xn0, float xn1) {
    int r0 = (int)floorf(xn0) + 1;
    int c0 = (int)floorf(xn1) + 1;
    r0 = min(max(r0, 0), GROWS - 4);
    c0 = min(max(c0, 0), GCOLS - 4);
    return r0 * GCOLS + c0;
}

// 4 points per thread: 8 independent stencil gathers in flight (MLP=8).
__global__ void __launch_bounds__(256) spline_kernel(
    const float4* __restrict__ x2, float4* __restrict__ out, int nquad)
{
    int i = blockIdx.x * blockDim.x + threadIdx.x;
    if (i >= nquad) return;

    // coords of points 4i..4i+3 : two float4 loads (coalesced pair)
    float4 pA = __ldg(&x2[2 * i]);
    float4 pB = __ldg(&x2[2 * i + 1]);

    float xn[4][2];
    xn[0][0] = fmaf(pA.x, 1024.0f, -0.5f);  xn[0][1] = fmaf(pA.y, 1024.0f, -0.5f);
    xn[1][0] = fmaf(pA.z, 1024.0f, -0.5f);  xn[1][1] = fmaf(pA.w, 1024.0f, -0.5f);
    xn[2][0] = fmaf(pB.x, 1024.0f, -0.5f);  xn[2][1] = fmaf(pB.y, 1024.0f, -0.5f);
    xn[3][0] = fmaf(pB.z, 1024.0f, -0.5f);  xn[3][1] = fmaf(pB.w, 1024.0f, -0.5f);

    const uint4* tab = reinterpret_cast<const uint4*>(g_pair);

    int base[4];
    #pragma unroll
    for (int k = 0; k < 4; k++) base[k] = stencil_base(xn[k][0], xn[k][1]);

    // Issue all 8 gathers before any consumption (MLP=8).
    uint4 va[4], vb[4];
    #pragma unroll
    for (int k = 0; k < 4; k++) va[k] = __ldg(tab + base[k]);
    #pragma unroll
    for (int k = 0; k < 4; k++) vb[k] = __ldg(tab + base[k] + 2 * GCOLS);

    float res[4];
    #pragma unroll
    for (int k = 0; k < 4; k++) {
        bool valid = (xn[k][0] > -2.0f) && (xn[k][0] < 1024.0f) &&
                     (xn[k][1] > -2.0f) && (xn[k][1] < 1024.0f);
        float r = eval_point(xn[k][0], xn[k][1], va[k], vb[k]);
        res[k] = valid ? r : 0.0f;
    }

    out[i] = make_float4(res[0], res[1], res[2], res[3]);
}

extern "C" void kernel_launch(void* const* d_in, const int* in_sizes, int n_in,
                              void* d_out, int out_size) {
    const float4* x2 = (const float4*)d_in[0];    // [N/2] float4 (2 points each)
    const float* coeffs = (const float*)d_in[1];  // [1028,1028] float32
    float4* out = (float4*)d_out;                 // [N/4] float4
    int n = out_size;                             // 2097152 (divisible by 4)
    int nquad = n >> 2;

    expand_kernel<<<(NCELL + 255) / 256, 256>>>(coeffs);
    spline_kernel<<<(nquad + 255) / 256, 256>>>(x2, out, nquad);
}